// round 11
// baseline (speedup 1.0000x reference)
#include <cuda_runtime.h>

// MakeCutouts: 64 cutouts of [4,3,512,512] fp32 -> bilinear 224x224, out [256,3,224,224].
//
// R9 predicated row-reuse + saturation tuning:
//  - __launch_bounds__(224, 6): regs==48 is exactly the 6-block reg limit;
//    declaring it lifts occupancy 50% -> ~65% (42 warps/SM).
//  - CHUNK=16: half the per-thread prolog, slightly better row reuse.
//  - unroll 2: batch next row-step's independent LDGs behind current consumers.
//  - planes split 6+6 (blockIdx.z); per-row 4 base pointers, plane loads by
//    immediate offset; row iy0 reused via warp-uniform predicate (off -> 0 wf);
//    coalesced __stcs stores protect the L2-resident input (64x reuse).

#define IMG   512
#define S     224
#define CUTN  64
#define NCH   12
#define PH    6
#define CHUNK 16
#define PLANE (IMG*IMG)
#define OPLANE (S*S)

__global__ __launch_bounds__(S, 6)
void make_cutouts_kernel(const float* __restrict__ x,
                         const int*   __restrict__ sizes,
                         const int*   __restrict__ offsetx,
                         const int*   __restrict__ offsety,
                         float*       __restrict__ out)
{
    const int j     = threadIdx.x;            // output column
    const int i0    = blockIdx.x * CHUNK;     // first output row of this chunk
    const int n     = blockIdx.y;             // cutout
    const int pbase = blockIdx.z * PH;        // plane half (0 or 6)

    const int   size  = __ldg(sizes + n);
    const float scale = (float)size * (1.0f / (float)S);
    const int   ox    = __ldg(offsetx + n);
    const int   oy    = __ldg(offsety + n);
    const int   sm1   = size - 1;

    // column taps (fixed for the whole walk)
    float srcx = fmaxf(scale * ((float)j + 0.5f) - 0.5f, 0.0f);
    int   ix0  = (int)floorf(srcx);
    const float fx = srcx - (float)ix0;       // frac before clamp (matches ref)
    ix0 = min(ix0, sm1);
    const int ix1 = min(ix0 + 1, sm1);
    const float wx1 = fx, wx0 = 1.0f - fx;

    const float* __restrict__ baseA = x + pbase * PLANE + (ox + ix0);
    const float* __restrict__ baseB = x + pbase * PLANE + (ox + ix1);

    float h1v[PH];                            // last blended source row, per plane
    int iy1_prev = -1000000;                  // sentinel: first row loads both

    float* __restrict__ op = out + ((n * NCH + pbase) * OPLANE + i0 * S + j);

    #pragma unroll 2
    for (int k = 0; k < CHUNK; ++k) {
        const int i = i0 + k;
        float srcy = fmaxf(scale * ((float)i + 0.5f) - 0.5f, 0.0f);
        int   iy0  = (int)floorf(srcy);
        const float fy = srcy - (float)iy0;
        iy0 = min(iy0, sm1);
        const int iy1 = min(iy0 + 1, sm1);
        const float wy1 = fy, wy0 = 1.0f - fy;

        const int r0 = (oy + iy0) * IMG;
        const int r1 = (oy + iy1) * IMG;
        const bool fresh = (iy0 != iy1_prev);     // warp-uniform

        // 4 row pointers; all plane loads below are [ptr + imm]
        const float* __restrict__ a0 = baseA + r0;
        const float* __restrict__ b0 = baseB + r0;
        const float* __restrict__ a1 = baseA + r1;
        const float* __restrict__ b1 = baseB + r1;

        #pragma unroll
        for (int p = 0; p < PH; ++p) {
            float h0;
            if (fresh) {                          // predicated; off -> 0 wavefronts
                h0 = fmaf(__ldg(b0 + p * PLANE), wx1,
                          __ldg(a0 + p * PLANE) * wx0);
            } else {
                h0 = h1v[p];
            }
            const float h1 = fmaf(__ldg(b1 + p * PLANE), wx1,
                                  __ldg(a1 + p * PLANE) * wx0);
            h1v[p] = h1;
            __stcs(op + p * OPLANE, fmaf(h1, wy1, h0 * wy0));
        }
        op += S;
        iy1_prev = iy1;
    }
}

extern "C" void kernel_launch(void* const* d_in, const int* in_sizes, int n_in,
                              void* d_out, int out_size)
{
    const float* x       = (const float*)d_in[0];
    const int*   sizes   = (const int*)d_in[1];
    const int*   offsetx = (const int*)d_in[2];
    const int*   offsety = (const int*)d_in[3];
    float* out = (float*)d_out;

    dim3 grid(S / CHUNK, CUTN, NCH / PH);   // 14 x 64 x 2
    dim3 block(S);                          // 224 threads; warp = 32 consecutive j
    make_cutouts_kernel<<<grid, block>>>(x, sizes, offsetx, offsety, out);
}

// round 12
// speedup vs baseline: 1.0951x; 1.0951x over previous
#include <cuda_runtime.h>

// MakeCutouts: 64 cutouts of [4,3,512,512] fp32 -> bilinear 224x224, out [256,3,224,224].
//
// Exact R9 algorithm (proven 49.5us, 48 regs) with ONE change: occupancy bound
// 5 -> 6 blocks/SM. 48 regs x 224 thr x 6 blocks = 64512 <= 65536, and ptxas's
// reg target under bound=6 is also 48, so no throttling is expected — this
// isolates the warp-count knob (35 -> 42 warps/SM) that R9's exposed-latency
// profile (L1 81%, issue 48%, occ 50%) says should push L1 toward saturation.
//
//  - planes split 6+6 (blockIdx.z); CHUNK=8 output rows per thread; unroll 1.
//  - per row-step: 4 precomputed row pointers, plane loads by immediate offset.
//  - row iy1 always fresh (strictly increasing); row iy0 reused via warp-uniform
//    predicate when it equals previous iy1 (predicated-off LDGs cost 0 wf).
//  - warp = 32 consecutive j -> coalesced __stcs stores; input stays L2-resident.

#define IMG   512
#define S     224
#define CUTN  64
#define NCH   12
#define PH    6
#define CHUNK 8
#define PLANE (IMG*IMG)
#define OPLANE (S*S)

__global__ __launch_bounds__(S, 6)
void make_cutouts_kernel(const float* __restrict__ x,
                         const int*   __restrict__ sizes,
                         const int*   __restrict__ offsetx,
                         const int*   __restrict__ offsety,
                         float*       __restrict__ out)
{
    const int j     = threadIdx.x;            // output column
    const int i0    = blockIdx.x * CHUNK;     // first output row of this chunk
    const int n     = blockIdx.y;             // cutout
    const int pbase = blockIdx.z * PH;        // plane half (0 or 6)

    const int   size  = __ldg(sizes + n);
    const float scale = (float)size * (1.0f / (float)S);
    const int   ox    = __ldg(offsetx + n);
    const int   oy    = __ldg(offsety + n);
    const int   sm1   = size - 1;

    // column taps (fixed for the whole walk)
    float srcx = fmaxf(scale * ((float)j + 0.5f) - 0.5f, 0.0f);
    int   ix0  = (int)floorf(srcx);
    const float fx = srcx - (float)ix0;       // frac before clamp (matches ref)
    ix0 = min(ix0, sm1);
    const int ix1 = min(ix0 + 1, sm1);
    const float wx1 = fx, wx0 = 1.0f - fx;

    const float* __restrict__ baseA = x + pbase * PLANE + (ox + ix0);
    const float* __restrict__ baseB = x + pbase * PLANE + (ox + ix1);

    float h1v[PH];                            // last blended source row, per plane
    int iy1_prev = -1000000;                  // sentinel: first row loads both

    float* __restrict__ op = out + ((n * NCH + pbase) * OPLANE + i0 * S + j);

    #pragma unroll 1
    for (int k = 0; k < CHUNK; ++k) {
        const int i = i0 + k;
        float srcy = fmaxf(scale * ((float)i + 0.5f) - 0.5f, 0.0f);
        int   iy0  = (int)floorf(srcy);
        const float fy = srcy - (float)iy0;
        iy0 = min(iy0, sm1);
        const int iy1 = min(iy0 + 1, sm1);
        const float wy1 = fy, wy0 = 1.0f - fy;

        const int r0 = (oy + iy0) * IMG;
        const int r1 = (oy + iy1) * IMG;
        const bool fresh = (iy0 != iy1_prev);     // warp-uniform

        // 4 row pointers; all plane loads below are [ptr + imm]
        const float* __restrict__ a0 = baseA + r0;
        const float* __restrict__ b0 = baseB + r0;
        const float* __restrict__ a1 = baseA + r1;
        const float* __restrict__ b1 = baseB + r1;

        #pragma unroll
        for (int p = 0; p < PH; ++p) {
            float h0;
            if (fresh) {                          // predicated; off -> 0 wavefronts
                h0 = fmaf(__ldg(b0 + p * PLANE), wx1,
                          __ldg(a0 + p * PLANE) * wx0);
            } else {
                h0 = h1v[p];
            }
            const float h1 = fmaf(__ldg(b1 + p * PLANE), wx1,
                                  __ldg(a1 + p * PLANE) * wx0);
            h1v[p] = h1;
            __stcs(op + p * OPLANE, fmaf(h1, wy1, h0 * wy0));
        }
        op += S;
        iy1_prev = iy1;
    }
}

extern "C" void kernel_launch(void* const* d_in, const int* in_sizes, int n_in,
                              void* d_out, int out_size)
{
    const float* x       = (const float*)d_in[0];
    const int*   sizes   = (const int*)d_in[1];
    const int*   offsetx = (const int*)d_in[2];
    const int*   offsety = (const int*)d_in[3];
    float* out = (float*)d_out;

    dim3 grid(S / CHUNK, CUTN, NCH / PH);   // 28 x 64 x 2
    dim3 block(S);                          // 224 threads; warp = 32 consecutive j
    make_cutouts_kernel<<<grid, block>>>(x, sizes, offsetx, offsety, out);
}

// round 15
// speedup vs baseline: 1.1228x; 1.0253x over previous
#include <cuda_runtime.h>

// MakeCutouts: 64 cutouts of [4,3,512,512] fp32 -> bilinear 224x224, out [256,3,224,224].
//
// Exact R9 algorithm/config (49.5us proven: CHUNK=8, PH=6, bound=5, 48 regs)
// with ONE change: the row loop is fully unrolled. Under bound=5 the reg cap is
// 56 (R9 used only 48), so ptxas can software-pipeline the next row-step's
// address-independent LDGs behind the current step's FMA consumers instead of
// stalling at the loop branch. (R11/R12 established that bound=6 throttles regs
// to 40 and loses; this keeps bound=5.)
//
//  - planes split 6+6 (blockIdx.z); per row-step 4 base pointers, plane loads
//    by immediate offset (p*PLANE*4 < 8MB imm).
//  - row iy1 always fresh (strictly increasing); row iy0 reused via warp-uniform
//    predicate when it equals previous iy1 (predicated-off LDGs cost 0 wf).
//  - warp = 32 consecutive j -> coalesced __stcs stores; input stays L2-resident.

#define IMG   512
#define S     224
#define CUTN  64
#define NCH   12
#define PH    6
#define CHUNK 8
#define PLANE (IMG*IMG)
#define OPLANE (S*S)

__global__ __launch_bounds__(S, 5)
void make_cutouts_kernel(const float* __restrict__ x,
                         const int*   __restrict__ sizes,
                         const int*   __restrict__ offsetx,
                         const int*   __restrict__ offsety,
                         float*       __restrict__ out)
{
    const int j     = threadIdx.x;            // output column
    const int i0    = blockIdx.x * CHUNK;     // first output row of this chunk
    const int n     = blockIdx.y;             // cutout
    const int pbase = blockIdx.z * PH;        // plane half (0 or 6)

    const int   size  = __ldg(sizes + n);
    const float scale = (float)size * (1.0f / (float)S);
    const int   ox    = __ldg(offsetx + n);
    const int   oy    = __ldg(offsety + n);
    const int   sm1   = size - 1;

    // column taps (fixed for the whole walk)
    float srcx = fmaxf(scale * ((float)j + 0.5f) - 0.5f, 0.0f);
    int   ix0  = (int)floorf(srcx);
    const float fx = srcx - (float)ix0;       // frac before clamp (matches ref)
    ix0 = min(ix0, sm1);
    const int ix1 = min(ix0 + 1, sm1);
    const float wx1 = fx, wx0 = 1.0f - fx;

    const float* __restrict__ baseA = x + pbase * PLANE + (ox + ix0);
    const float* __restrict__ baseB = x + pbase * PLANE + (ox + ix1);

    float h1v[PH];                            // last blended source row, per plane
    int iy1_prev = -1000000;                  // sentinel: first row loads both

    float* __restrict__ op = out + ((n * NCH + pbase) * OPLANE + i0 * S + j);

    #pragma unroll
    for (int k = 0; k < CHUNK; ++k) {
        const int i = i0 + k;
        float srcy = fmaxf(scale * ((float)i + 0.5f) - 0.5f, 0.0f);
        int   iy0  = (int)floorf(srcy);
        const float fy = srcy - (float)iy0;
        iy0 = min(iy0, sm1);
        const int iy1 = min(iy0 + 1, sm1);
        const float wy1 = fy, wy0 = 1.0f - fy;

        const int r0 = (oy + iy0) * IMG;
        const int r1 = (oy + iy1) * IMG;
        const bool fresh = (iy0 != iy1_prev);     // warp-uniform

        // 4 row pointers; all plane loads below are [ptr + imm]
        const float* __restrict__ a0 = baseA + r0;
        const float* __restrict__ b0 = baseB + r0;
        const float* __restrict__ a1 = baseA + r1;
        const float* __restrict__ b1 = baseB + r1;

        #pragma unroll
        for (int p = 0; p < PH; ++p) {
            float h0;
            if (fresh) {                          // predicated; off -> 0 wavefronts
                h0 = fmaf(__ldg(b0 + p * PLANE), wx1,
                          __ldg(a0 + p * PLANE) * wx0);
            } else {
                h0 = h1v[p];
            }
            const float h1 = fmaf(__ldg(b1 + p * PLANE), wx1,
                                  __ldg(a1 + p * PLANE) * wx0);
            h1v[p] = h1;
            __stcs(op + p * OPLANE, fmaf(h1, wy1, h0 * wy0));
        }
        op += S;
        iy1_prev = iy1;
    }
}

extern "C" void kernel_launch(void* const* d_in, const int* in_sizes, int n_in,
                              void* d_out, int out_size)
{
    const float* x       = (const float*)d_in[0];
    const int*   sizes   = (const int*)d_in[1];
    const int*   offsetx = (const int*)d_in[2];
    const int*   offsety = (const int*)d_in[3];
    float* out = (float*)d_out;

    dim3 grid(S / CHUNK, CUTN, NCH / PH);   // 28 x 64 x 2
    dim3 block(S);                          // 224 threads; warp = 32 consecutive j
    make_cutouts_kernel<<<grid, block>>>(x, sizes, offsetx, offsety, out);
}